// round 4
// baseline (speedup 1.0000x reference)
#include <cuda_runtime.h>
#include <math.h>

#define FIN 512
#define HD  16
#define CD  7
#define NMAX 100000
#define EMAX 3200000

typedef unsigned long long u64;

// ---------------- scratch (static device globals) ----------------
__device__ int   g_cnt [NMAX];        // in-degree (without self-loop)
__device__ int   g_rows[NMAX];        // CSR row start
__device__ int   g_cur [NMAX];        // fill cursor
__device__ int   g_bsum[128];         // scan block sums
__device__ float g_dinv[NMAX];
__device__ int2  g_edge[EMAX];        // {src, bitcast(dinv[src])}
__device__ float g_h1  [NMAX * HD];
__device__ float g_h2  [NMAX * 8];    // 7 classes padded to 8 (col7 == 0)
__device__ volatile int g_bar;        // spin-barrier arrive counter
__device__ volatile int g_flag;       // spin-barrier release flag

// ---------------- f32x2 helpers ----------------
__device__ __forceinline__ u64 pk2(float lo, float hi) {
    u64 r; asm("mov.b64 %0, {%1, %2};" : "=l"(r) : "f"(lo), "f"(hi)); return r;
}
__device__ __forceinline__ void upk2(float& lo, float& hi, u64 v) {
    asm("mov.b64 {%0, %1}, %2;" : "=f"(lo), "=f"(hi) : "l"(v));
}
__device__ __forceinline__ void fma2(u64& d, u64 a, u64 b) {
    asm("fma.rn.f32x2 %0, %1, %2, %0;" : "+l"(d) : "l"(a), "l"(b));
}

// ---------------- GEMM1 block: h1[tile] = x[tile] @ W1 ----------------
// 256 threads -> 256 nodes x 16 cols. Thread (ng=t>>2, jg=t&3) owns nodes
// ng*4..+3 x cols jg*4..+3, accumulated as f32x2 node-pairs.
// x staged global->regs->smem (k-major, stride 260, 16B-aligned rows).
// W pre-packed as broadcast f32x2 pairs in smem (no per-iter packing).
__device__ __forceinline__ void gemm1_block(const float* __restrict__ x,
                                            const float* __restrict__ W1,
                                            int n, int bid) {
    __shared__ u64   sWp[32 * 16];       // [k][j] broadcast pair, 4KB
    __shared__ float sXT[32 * 260];      // k-major: [k][node], stride 260

    const int t  = threadIdx.x;
    const int n0 = bid * 256;
    const int ng = t >> 2;
    const int jg = t & 3;

    u64 acc[2][4];
#pragma unroll
    for (int p = 0; p < 2; p++)
#pragma unroll
        for (int c = 0; c < 4; c++) acc[p][c] = 0ull;

    float4 rx[8];
    float4 rw = make_float4(0.f, 0.f, 0.f, 0.f);

    // prologue: stage tile k0=0
    if (t < 128) rw = *(const float4*)(W1 + (size_t)(t >> 2) * HD + (t & 3) * 4);
#pragma unroll
    for (int i = 0; i < 8; i++) {
        int f = t + 256 * i;
        int node = n0 + (f >> 3);
        int kq = f & 7;
        rx[i] = (node < n) ? *(const float4*)(x + (size_t)node * FIN + kq * 4)
                           : make_float4(0.f, 0.f, 0.f, 0.f);
    }

#pragma unroll 1
    for (int k0 = 0; k0 < FIN; k0 += 32) {
        if (t < 128) {
            u64* wp = &sWp[(t >> 2) * 16 + (t & 3) * 4];
            wp[0] = pk2(rw.x, rw.x);
            wp[1] = pk2(rw.y, rw.y);
            wp[2] = pk2(rw.z, rw.z);
            wp[3] = pk2(rw.w, rw.w);
        }
#pragma unroll
        for (int i = 0; i < 8; i++) {
            int f = t + 256 * i;
            int nl = f >> 3;
            int kq = f & 7;
            float* sp = &sXT[(kq * 4) * 260 + nl];
            sp[0]   = rx[i].x;
            sp[260] = rx[i].y;
            sp[520] = rx[i].z;
            sp[780] = rx[i].w;
        }
        __syncthreads();
        bool more = (k0 + 32 < FIN);
        if (more) {   // prefetch next tile while computing (LDGs in flight)
            if (t < 128)
                rw = *(const float4*)(W1 + (size_t)(k0 + 32 + (t >> 2)) * HD + (t & 3) * 4);
#pragma unroll
            for (int i = 0; i < 8; i++) {
                int f = t + 256 * i;
                int node = n0 + (f >> 3);
                int kq = f & 7;
                rx[i] = (node < n)
                      ? *(const float4*)(x + (size_t)node * FIN + k0 + 32 + kq * 4)
                      : make_float4(0.f, 0.f, 0.f, 0.f);
            }
        }
#pragma unroll
        for (int k = 0; k < 32; k++) {
            const float* xb = &sXT[k * 260 + ng * 4];   // 16B aligned
            u64 x01 = *(const u64*)xb;
            u64 x23 = *(const u64*)(xb + 2);
            const u64* wb = &sWp[k * 16 + jg * 4];      // 32B aligned
            fma2(acc[0][0], x01, wb[0]); fma2(acc[1][0], x23, wb[0]);
            fma2(acc[0][1], x01, wb[1]); fma2(acc[1][1], x23, wb[1]);
            fma2(acc[0][2], x01, wb[2]); fma2(acc[1][2], x23, wb[2]);
            fma2(acc[0][3], x01, wb[3]); fma2(acc[1][3], x23, wb[3]);
        }
        if (more) __syncthreads();
    }

#pragma unroll
    for (int p = 0; p < 2; p++) {
        float lo[4], hi[4];
#pragma unroll
        for (int c = 0; c < 4; c++) upk2(lo[c], hi[c], acc[p][c]);
        int node0 = n0 + ng * 4 + p * 2;
        if (node0 < n)
            *(float4*)&g_h1[(size_t)node0 * HD + jg * 4] =
                make_float4(lo[0], lo[1], lo[2], lo[3]);
        if (node0 + 1 < n)
            *(float4*)&g_h1[(size_t)(node0 + 1) * HD + jg * 4] =
                make_float4(hi[0], hi[1], hi[2], hi[3]);
    }
}

// ---------------- zero + barrier reset ----------------

__global__ void k_zero(int n) {
    int i = blockIdx.x * blockDim.x + threadIdx.x;
    if (i < n) g_cnt[i] = 0;
    if (i == 0) { g_bar = 0; g_flag = 0; }
}

// ---------------- fused launches: CSR work overlapped with GEMM ----------------

// launch A: [0,gemmBlocks) run GEMM part A; rest count in-degrees (grid-stride)
__global__ __launch_bounds__(256, 2) void kA(const int* __restrict__ dst, int e,
                                             const float* __restrict__ x,
                                             const float* __restrict__ W1, int n,
                                             int gemmBlocks) {
    if ((int)blockIdx.x < gemmBlocks) { gemm1_block(x, W1, n, blockIdx.x); return; }
    int nb = gridDim.x - gemmBlocks;
    int b  = blockIdx.x - gemmBlocks;
    for (int i = b * 256 + threadIdx.x; i < e; i += nb * 256)
        atomicAdd(&g_cnt[dst[i]], 1);
}

// launch B: [0,gemmBlocks) run GEMM part B; rest fill CSR (grid-stride)
__global__ __launch_bounds__(256, 2) void kB(const int* __restrict__ src,
                                             const int* __restrict__ dst, int e,
                                             const float* __restrict__ x,
                                             const float* __restrict__ W1, int n,
                                             int gemmBlocks, int gemmOffset) {
    if ((int)blockIdx.x < gemmBlocks) {
        gemm1_block(x, W1, n, gemmOffset + blockIdx.x);
        return;
    }
    int nb = gridDim.x - gemmBlocks;
    int b  = blockIdx.x - gemmBlocks;
    for (int i = b * 256 + threadIdx.x; i < e; i += nb * 256) {
        int s = src[i], d = dst[i];
        int pos = atomicAdd(&g_cur[d], 1);
        g_edge[pos] = make_int2(s, __float_as_int(g_dinv[s]));
    }
}

// ---------------- single-kernel scan (+rsqrt) with device barrier ----------------
// Grid must be <= 148 blocks (all resident). nb = ceil(n/1024) = 98 here.

__global__ __launch_bounds__(256) void k_scan_all(int n, int nb) {
    __shared__ int s[256];
    const int t = threadIdx.x;
    const int b = blockIdx.x;

    // phase 1: per-block exclusive scan of g_cnt[1024 chunk], plus dinv
    int base = b * 1024 + t * 4;
    int v0 = (base + 0 < n) ? g_cnt[base + 0] : 0;
    int v1 = (base + 1 < n) ? g_cnt[base + 1] : 0;
    int v2 = (base + 2 < n) ? g_cnt[base + 2] : 0;
    int v3 = (base + 3 < n) ? g_cnt[base + 3] : 0;
    if (base + 0 < n) g_dinv[base + 0] = rsqrtf((float)(v0 + 1));
    if (base + 1 < n) g_dinv[base + 1] = rsqrtf((float)(v1 + 1));
    if (base + 2 < n) g_dinv[base + 2] = rsqrtf((float)(v2 + 1));
    if (base + 3 < n) g_dinv[base + 3] = rsqrtf((float)(v3 + 1));
    int ts = v0 + v1 + v2 + v3;
    s[t] = ts;
    __syncthreads();
#pragma unroll
    for (int off = 1; off < 256; off <<= 1) {
        int xv = (t >= off) ? s[t - off] : 0;
        __syncthreads();
        s[t] += xv;
        __syncthreads();
    }
    int excl = s[t] - ts;

    // publish block total, arrive
    if (t == 255) {
        g_bsum[b] = s[255];
        __threadfence();
        atomicAdd((int*)&g_bar, 1);
    }

    // phase 2: block 0 scans block sums, releases
    if (b == 0) {
        if (t == 0) {
            while (g_bar < nb) { }
            int acc2 = 0;
            for (int i = 0; i < nb; i++) { int v = g_bsum[i]; g_bsum[i] = acc2; acc2 += v; }
            __threadfence();
            g_flag = 1;
        }
        __syncthreads();
    } else {
        if (t == 0) {
            while (g_flag == 0) { }
            __threadfence();
        }
        __syncthreads();
    }

    // phase 3: add block offset, write rows + cursors
    int off = g_bsum[b];
    int r = excl + off;
    if (base + 0 < n) { g_rows[base + 0] = r; g_cur[base + 0] = r; r += v0; }
    if (base + 1 < n) { g_rows[base + 1] = r; g_cur[base + 1] = r; r += v1; }
    if (base + 2 < n) { g_rows[base + 2] = r; g_cur[base + 2] = r; r += v2; }
    if (base + 3 < n) { g_rows[base + 3] = r; g_cur[base + 3] = r; }
}

// ---------------- agg layer 1 + fused layer-2 transform ----------------

__global__ __launch_bounds__(256) void k_agg1(const float* __restrict__ b1,
                                              const float* __restrict__ W2, int n) {
    __shared__ float sW2[HD * 8];
    __shared__ float sb1[HD];
    int t = threadIdx.x;
    if (t < HD * 8) {
        int j = t >> 3, cc = t & 7;
        sW2[t] = (cc < CD) ? W2[j * CD + cc] : 0.f;
    } else if (t < HD * 8 + HD) {
        sb1[t - HD * 8] = b1[t - HD * 8];
    }
    __syncthreads();

    int node = blockIdx.x * 64 + (t >> 2);
    int c = t & 3;
    bool valid = node < n;
    if (!valid) node = n - 1;

    float dv = g_dinv[node];
    float4 h = *(const float4*)(g_h1 + (size_t)node * HD + c * 4);
    float4 acc = make_float4(h.x * dv, h.y * dv, h.z * dv, h.w * dv);

    int st = g_rows[node], cnt = g_cnt[node];
    int j = 0;
    for (; j + 1 < cnt; j += 2) {
        int2 e0 = g_edge[st + j], e1 = g_edge[st + j + 1];
        float m0 = __int_as_float(e0.y), m1 = __int_as_float(e1.y);
        float4 v0 = *(const float4*)(g_h1 + (size_t)e0.x * HD + c * 4);
        float4 v1 = *(const float4*)(g_h1 + (size_t)e1.x * HD + c * 4);
        acc.x += v0.x * m0 + v1.x * m1;
        acc.y += v0.y * m0 + v1.y * m1;
        acc.z += v0.z * m0 + v1.z * m1;
        acc.w += v0.w * m0 + v1.w * m1;
    }
    if (j < cnt) {
        int2 e0 = g_edge[st + j];
        float m0 = __int_as_float(e0.y);
        float4 v0 = *(const float4*)(g_h1 + (size_t)e0.x * HD + c * 4);
        acc.x += v0.x * m0; acc.y += v0.y * m0;
        acc.z += v0.z * m0; acc.w += v0.w * m0;
    }

    float v0 = fmaxf(acc.x * dv + sb1[c * 4 + 0], 0.f);
    float v1 = fmaxf(acc.y * dv + sb1[c * 4 + 1], 0.f);
    float v2 = fmaxf(acc.z * dv + sb1[c * 4 + 2], 0.f);
    float v3 = fmaxf(acc.w * dv + sb1[c * 4 + 3], 0.f);

    float p[8];
#pragma unroll
    for (int cc = 0; cc < 8; cc++) {
        p[cc] = v0 * sW2[(c * 4 + 0) * 8 + cc]
              + v1 * sW2[(c * 4 + 1) * 8 + cc]
              + v2 * sW2[(c * 4 + 2) * 8 + cc]
              + v3 * sW2[(c * 4 + 3) * 8 + cc];
    }
#pragma unroll
    for (int cc = 0; cc < 8; cc++) {
        p[cc] += __shfl_xor_sync(0xFFFFFFFFu, p[cc], 1);
        p[cc] += __shfl_xor_sync(0xFFFFFFFFu, p[cc], 2);
    }
    if (valid) {
        if (c == 0)
            *(float4*)(g_h2 + (size_t)node * 8)     = make_float4(p[0], p[1], p[2], p[3]);
        else if (c == 1)
            *(float4*)(g_h2 + (size_t)node * 8 + 4) = make_float4(p[4], p[5], p[6], 0.f);
    }
}

// ---------------- agg layer 2 + fused bias + log_softmax ----------------

__global__ __launch_bounds__(256) void k_agg2(const float* __restrict__ b2,
                                              float* __restrict__ out, int n) {
    __shared__ float sb2[8];
    int t = threadIdx.x;
    if (t < 8) sb2[t] = (t < CD) ? b2[t] : -1e30f;   // pad lane -> exp()==0
    __syncthreads();

    int node = blockIdx.x * 128 + (t >> 1);
    int c = t & 1;
    bool valid = node < n;
    if (!valid) node = n - 1;

    float dv = g_dinv[node];
    float4 h = *(const float4*)(g_h2 + (size_t)node * 8 + c * 4);
    float4 acc = make_float4(h.x * dv, h.y * dv, h.z * dv, h.w * dv);

    int st = g_rows[node], cnt = g_cnt[node];
    int j = 0;
    for (; j + 1 < cnt; j += 2) {
        int2 e0 = g_edge[st + j], e1 = g_edge[st + j + 1];
        float m0 = __int_as_float(e0.y), m1 = __int_as_float(e1.y);
        float4 v0 = *(const float4*)(g_h2 + (size_t)e0.x * 8 + c * 4);
        float4 v1 = *(const float4*)(g_h2 + (size_t)e1.x * 8 + c * 4);
        acc.x += v0.x * m0 + v1.x * m1;
        acc.y += v0.y * m0 + v1.y * m1;
        acc.z += v0.z * m0 + v1.z * m1;
        acc.w += v0.w * m0 + v1.w * m1;
    }
    if (j < cnt) {
        int2 e0 = g_edge[st + j];
        float m0 = __int_as_float(e0.y);
        float4 v0 = *(const float4*)(g_h2 + (size_t)e0.x * 8 + c * 4);
        acc.x += v0.x * m0; acc.y += v0.y * m0;
        acc.z += v0.z * m0; acc.w += v0.w * m0;
    }

    float o0 = acc.x * dv + sb2[c * 4 + 0];
    float o1 = acc.y * dv + sb2[c * 4 + 1];
    float o2 = acc.z * dv + sb2[c * 4 + 2];
    float o3 = acc.w * dv + sb2[c * 4 + 3];

    float m = fmaxf(fmaxf(o0, o1), fmaxf(o2, o3));
    m = fmaxf(m, __shfl_xor_sync(0xFFFFFFFFu, m, 1));
    float s = expf(o0 - m) + expf(o1 - m) + expf(o2 - m) + expf(o3 - m);
    s += __shfl_xor_sync(0xFFFFFFFFu, s, 1);
    float l = m + logf(s);

    if (valid) {
        float* op = out + (size_t)node * CD + c * 4;
        op[0] = o0 - l; op[1] = o1 - l; op[2] = o2 - l;
        if (c == 0) op[3] = o3 - l;
    }
}

// ---------------- launch ----------------

extern "C" void kernel_launch(void* const* d_in, const int* in_sizes, int n_in,
                              void* d_out, int out_size) {
    const float* x  = (const float*)d_in[0];
    const int*   ei = (const int*)  d_in[1];
    const float* W1 = (const float*)d_in[2];
    const float* b1 = (const float*)d_in[3];
    const float* W2 = (const float*)d_in[4];
    const float* b2 = (const float*)d_in[5];

    const int n = in_sizes[0] / FIN;
    const int e = in_sizes[1] / 2;
    const int* src = ei;
    const int* dst = ei + e;

    const int NB = (n + 255) / 256;        // gemm node-blocks (391)
    const int GA = NB / 5;                 // gemm part A (overlaps edge count)
    const int GB = NB - GA;                // gemm part B (overlaps CSR fill)
    const int nbScan = (n + 1023) / 1024;  // 98 <= 148 (must stay resident)

    k_zero     <<<(n + 255) / 256, 256>>>(n);
    kA         <<<GA + 768, 256>>>(dst, e, x, W1, n, GA);
    k_scan_all <<<nbScan, 256>>>(n, nbScan);
    kB         <<<GB + 1536, 256>>>(src, dst, e, x, W1, n, GB, GA);
    k_agg1     <<<(n + 63) / 64, 256>>>(b1, W2, n);
    k_agg2     <<<(n + 127) / 128, 256>>>(b2, (float*)d_out, n);
}

// round 5
// speedup vs baseline: 1.1242x; 1.1242x over previous
#include <cuda_runtime.h>
#include <math.h>

#define FIN 512
#define HD  16
#define CD  7
#define NMAX 100000
#define EMAX 3200000

typedef unsigned long long u64;

// ---------------- scratch (static device globals) ----------------
__device__ int   g_cnt [NMAX];        // in-degree (without self-loop)
__device__ int   g_rows[NMAX];        // CSR row start
__device__ int   g_cur [NMAX];        // fill cursor
__device__ int   g_bsum[128];         // scan block sums
__device__ float g_dinv[NMAX];
__device__ int   g_esrc[EMAX];        // CSR: source node per edge slot
__device__ float g_h1  [NMAX * HD];
__device__ float g_h2  [NMAX * 8];    // 7 classes padded to 8 (col7 == 0)
__device__ volatile int g_bar;        // spin-barrier arrive counter
__device__ volatile int g_flag;       // spin-barrier release flag

// ---------------- f32x2 helpers ----------------
__device__ __forceinline__ u64 pk2(float lo, float hi) {
    u64 r; asm("mov.b64 %0, {%1, %2};" : "=l"(r) : "f"(lo), "f"(hi)); return r;
}
__device__ __forceinline__ void upk2(float& lo, float& hi, u64 v) {
    asm("mov.b64 {%0, %1}, %2;" : "=f"(lo), "=f"(hi) : "l"(v));
}
__device__ __forceinline__ void fma2(u64& d, u64 a, u64 b) {
    asm("fma.rn.f32x2 %0, %1, %2, %0;" : "+l"(d) : "l"(a), "l"(b));
}

// ---------------- GEMM1 block: h1[tile] = x[tile] @ W1 ----------------
// 256 threads -> 256 nodes x 16 cols. Thread (ng=t>>2, jg=t&3) owns nodes
// ng*4..+3 x cols jg*4..+3, accumulated as f32x2 node-pairs.
// x staged global->regs->smem (k-major, stride 260, 16B-aligned rows).
__device__ __forceinline__ void gemm1_block(const float* __restrict__ x,
                                            const float* __restrict__ W1,
                                            int n, int bid) {
    __shared__ float4 sW4[128];          // 32 k x 16 j
    __shared__ float  sXT[32 * 260];     // k-major: [k][node], stride 260

    const int t  = threadIdx.x;
    const int n0 = bid * 256;
    const int ng = t >> 2;
    const int jg = t & 3;

    u64 acc[2][4];
#pragma unroll
    for (int p = 0; p < 2; p++)
#pragma unroll
        for (int c = 0; c < 4; c++) acc[p][c] = 0ull;

    float4 rx[8];
    float4 rw = make_float4(0.f, 0.f, 0.f, 0.f);

    // prologue: stage tile k0=0
    if (t < 128) rw = *(const float4*)(W1 + (size_t)(t >> 2) * HD + (t & 3) * 4);
#pragma unroll
    for (int i = 0; i < 8; i++) {
        int f = t + 256 * i;
        int node = n0 + (f >> 3);
        int kq = f & 7;
        rx[i] = (node < n) ? *(const float4*)(x + (size_t)node * FIN + kq * 4)
                           : make_float4(0.f, 0.f, 0.f, 0.f);
    }

#pragma unroll 1
    for (int k0 = 0; k0 < FIN; k0 += 32) {
        if (t < 128) sW4[t] = rw;
#pragma unroll
        for (int i = 0; i < 8; i++) {
            int f = t + 256 * i;
            int nl = f >> 3;
            int kq = f & 7;
            float* sp = &sXT[(kq * 4) * 260 + nl];
            sp[0]   = rx[i].x;
            sp[260] = rx[i].y;
            sp[520] = rx[i].z;
            sp[780] = rx[i].w;
        }
        __syncthreads();
        bool more = (k0 + 32 < FIN);
        if (more) {   // prefetch next tile while computing (LDGs in flight)
            if (t < 128)
                rw = *(const float4*)(W1 + (size_t)(k0 + 32 + (t >> 2)) * HD + (t & 3) * 4);
#pragma unroll
            for (int i = 0; i < 8; i++) {
                int f = t + 256 * i;
                int node = n0 + (f >> 3);
                int kq = f & 7;
                rx[i] = (node < n)
                      ? *(const float4*)(x + (size_t)node * FIN + k0 + 32 + kq * 4)
                      : make_float4(0.f, 0.f, 0.f, 0.f);
            }
        }
#pragma unroll
        for (int k = 0; k < 32; k++) {
            const float* xb = &sXT[k * 260 + ng * 4];   // 16B aligned
            u64 x01 = *(const u64*)xb;
            u64 x23 = *(const u64*)(xb + 2);
            float4 wv = sW4[k * 4 + jg];
            u64 w0 = pk2(wv.x, wv.x);
            u64 w1 = pk2(wv.y, wv.y);
            u64 w2 = pk2(wv.z, wv.z);
            u64 w3 = pk2(wv.w, wv.w);
            fma2(acc[0][0], x01, w0); fma2(acc[1][0], x23, w0);
            fma2(acc[0][1], x01, w1); fma2(acc[1][1], x23, w1);
            fma2(acc[0][2], x01, w2); fma2(acc[1][2], x23, w2);
            fma2(acc[0][3], x01, w3); fma2(acc[1][3], x23, w3);
        }
        if (more) __syncthreads();
    }

#pragma unroll
    for (int p = 0; p < 2; p++) {
        float lo[4], hi[4];
#pragma unroll
        for (int c = 0; c < 4; c++) upk2(lo[c], hi[c], acc[p][c]);
        int node0 = n0 + ng * 4 + p * 2;
        if (node0 < n)
            *(float4*)&g_h1[(size_t)node0 * HD + jg * 4] =
                make_float4(lo[0], lo[1], lo[2], lo[3]);
        if (node0 + 1 < n)
            *(float4*)&g_h1[(size_t)(node0 + 1) * HD + jg * 4] =
                make_float4(hi[0], hi[1], hi[2], hi[3]);
    }
}

// ---------------- zero + barrier reset ----------------

__global__ void k_zero(int n) {
    int i = blockIdx.x * blockDim.x + threadIdx.x;
    if (i < n) g_cnt[i] = 0;
    if (i == 0) { g_bar = 0; g_flag = 0; }
}

// ---------------- fused launches: CSR work overlapped with GEMM ----------------

// launch A: [0,gemmBlocks) run GEMM part A; rest count in-degrees (grid-stride)
__global__ __launch_bounds__(256, 2) void kA(const int* __restrict__ dst, int e,
                                             const float* __restrict__ x,
                                             const float* __restrict__ W1, int n,
                                             int gemmBlocks) {
    if ((int)blockIdx.x < gemmBlocks) { gemm1_block(x, W1, n, blockIdx.x); return; }
    int nb = gridDim.x - gemmBlocks;
    int b  = blockIdx.x - gemmBlocks;
    for (int i = b * 256 + threadIdx.x; i < e; i += nb * 256)
        atomicAdd(&g_cnt[dst[i]], 1);
}

// launch B: [0,gemmBlocks) run GEMM part B; rest fill CSR (grid-stride)
__global__ __launch_bounds__(256, 2) void kB(const int* __restrict__ src,
                                             const int* __restrict__ dst, int e,
                                             const float* __restrict__ x,
                                             const float* __restrict__ W1, int n,
                                             int gemmBlocks, int gemmOffset) {
    if ((int)blockIdx.x < gemmBlocks) {
        gemm1_block(x, W1, n, gemmOffset + blockIdx.x);
        return;
    }
    int nb = gridDim.x - gemmBlocks;
    int b  = blockIdx.x - gemmBlocks;
    for (int i = b * 256 + threadIdx.x; i < e; i += nb * 256) {
        int s = src[i], d = dst[i];
        int pos = atomicAdd(&g_cur[d], 1);
        g_esrc[pos] = s;
    }
}

// ---------------- single-kernel scan (+rsqrt) with device barrier ----------------
// Grid must be <= 148 blocks (all resident). nb = ceil(n/1024) = 98 here.

__global__ __launch_bounds__(256) void k_scan_all(int n, int nb) {
    __shared__ int s[256];
    const int t = threadIdx.x;
    const int b = blockIdx.x;

    int base = b * 1024 + t * 4;
    int v0 = (base + 0 < n) ? g_cnt[base + 0] : 0;
    int v1 = (base + 1 < n) ? g_cnt[base + 1] : 0;
    int v2 = (base + 2 < n) ? g_cnt[base + 2] : 0;
    int v3 = (base + 3 < n) ? g_cnt[base + 3] : 0;
    if (base + 0 < n) g_dinv[base + 0] = rsqrtf((float)(v0 + 1));
    if (base + 1 < n) g_dinv[base + 1] = rsqrtf((float)(v1 + 1));
    if (base + 2 < n) g_dinv[base + 2] = rsqrtf((float)(v2 + 1));
    if (base + 3 < n) g_dinv[base + 3] = rsqrtf((float)(v3 + 1));
    int ts = v0 + v1 + v2 + v3;
    s[t] = ts;
    __syncthreads();
#pragma unroll
    for (int off = 1; off < 256; off <<= 1) {
        int xv = (t >= off) ? s[t - off] : 0;
        __syncthreads();
        s[t] += xv;
        __syncthreads();
    }
    int excl = s[t] - ts;

    if (t == 255) {
        g_bsum[b] = s[255];
        __threadfence();
        atomicAdd((int*)&g_bar, 1);
    }

    if (b == 0) {
        if (t == 0) {
            while (g_bar < nb) { }
            int acc2 = 0;
            for (int i = 0; i < nb; i++) { int v = g_bsum[i]; g_bsum[i] = acc2; acc2 += v; }
            __threadfence();
            g_flag = 1;
        }
        __syncthreads();
    } else {
        if (t == 0) {
            while (g_flag == 0) { }
            __threadfence();
        }
        __syncthreads();
    }

    int off = g_bsum[b];
    int r = excl + off;
    if (base + 0 < n) { g_rows[base + 0] = r; g_cur[base + 0] = r; r += v0; }
    if (base + 1 < n) { g_rows[base + 1] = r; g_cur[base + 1] = r; r += v1; }
    if (base + 2 < n) { g_rows[base + 2] = r; g_cur[base + 2] = r; r += v2; }
    if (base + 3 < n) { g_rows[base + 3] = r; g_cur[base + 3] = r; }
}

// ---------------- agg layer 1 + fused layer-2 transform ----------------
// 4 lanes per node; lane c owns feats [4c,4c+4). dinv[s] gathered from L2.

__global__ __launch_bounds__(256) void k_agg1(const float* __restrict__ b1,
                                              const float* __restrict__ W2, int n) {
    __shared__ float sW2[HD * 8];
    __shared__ float sb1[HD];
    int t = threadIdx.x;
    if (t < HD * 8) {
        int j = t >> 3, cc = t & 7;
        sW2[t] = (cc < CD) ? W2[j * CD + cc] : 0.f;
    } else if (t < HD * 8 + HD) {
        sb1[t - HD * 8] = b1[t - HD * 8];
    }
    __syncthreads();

    int node = blockIdx.x * 64 + (t >> 2);
    int c = t & 3;
    bool valid = node < n;
    if (!valid) node = n - 1;

    float dv = g_dinv[node];
    float4 h = *(const float4*)(g_h1 + (size_t)node * HD + c * 4);
    float4 acc = make_float4(h.x * dv, h.y * dv, h.z * dv, h.w * dv);

    int st = g_rows[node], cnt = g_cnt[node];
    int j = 0;
    for (; j + 1 < cnt; j += 2) {
        int s0 = g_esrc[st + j], s1 = g_esrc[st + j + 1];
        float m0 = g_dinv[s0],   m1 = g_dinv[s1];
        float4 v0 = *(const float4*)(g_h1 + (size_t)s0 * HD + c * 4);
        float4 v1 = *(const float4*)(g_h1 + (size_t)s1 * HD + c * 4);
        acc.x += v0.x * m0 + v1.x * m1;
        acc.y += v0.y * m0 + v1.y * m1;
        acc.z += v0.z * m0 + v1.z * m1;
        acc.w += v0.w * m0 + v1.w * m1;
    }
    if (j < cnt) {
        int s0 = g_esrc[st + j];
        float m0 = g_dinv[s0];
        float4 v0 = *(const float4*)(g_h1 + (size_t)s0 * HD + c * 4);
        acc.x += v0.x * m0; acc.y += v0.y * m0;
        acc.z += v0.z * m0; acc.w += v0.w * m0;
    }

    float v0 = fmaxf(acc.x * dv + sb1[c * 4 + 0], 0.f);
    float v1 = fmaxf(acc.y * dv + sb1[c * 4 + 1], 0.f);
    float v2 = fmaxf(acc.z * dv + sb1[c * 4 + 2], 0.f);
    float v3 = fmaxf(acc.w * dv + sb1[c * 4 + 3], 0.f);

    float p[8];
#pragma unroll
    for (int cc = 0; cc < 8; cc++) {
        p[cc] = v0 * sW2[(c * 4 + 0) * 8 + cc]
              + v1 * sW2[(c * 4 + 1) * 8 + cc]
              + v2 * sW2[(c * 4 + 2) * 8 + cc]
              + v3 * sW2[(c * 4 + 3) * 8 + cc];
    }
#pragma unroll
    for (int cc = 0; cc < 8; cc++) {
        p[cc] += __shfl_xor_sync(0xFFFFFFFFu, p[cc], 1);
        p[cc] += __shfl_xor_sync(0xFFFFFFFFu, p[cc], 2);
    }
    if (valid) {
        if (c == 0)
            *(float4*)(g_h2 + (size_t)node * 8)     = make_float4(p[0], p[1], p[2], p[3]);
        else if (c == 1)
            *(float4*)(g_h2 + (size_t)node * 8 + 4) = make_float4(p[4], p[5], p[6], 0.f);
    }
}

// ---------------- agg layer 2 + fused bias + log_softmax ----------------

__global__ __launch_bounds__(256) void k_agg2(const float* __restrict__ b2,
                                              float* __restrict__ out, int n) {
    __shared__ float sb2[8];
    int t = threadIdx.x;
    if (t < 8) sb2[t] = (t < CD) ? b2[t] : -1e30f;   // pad lane -> exp()==0
    __syncthreads();

    int node = blockIdx.x * 128 + (t >> 1);
    int c = t & 1;
    bool valid = node < n;
    if (!valid) node = n - 1;

    float dv = g_dinv[node];
    float4 h = *(const float4*)(g_h2 + (size_t)node * 8 + c * 4);
    float4 acc = make_float4(h.x * dv, h.y * dv, h.z * dv, h.w * dv);

    int st = g_rows[node], cnt = g_cnt[node];
    int j = 0;
    for (; j + 1 < cnt; j += 2) {
        int s0 = g_esrc[st + j], s1 = g_esrc[st + j + 1];
        float m0 = g_dinv[s0],   m1 = g_dinv[s1];
        float4 v0 = *(const float4*)(g_h2 + (size_t)s0 * 8 + c * 4);
        float4 v1 = *(const float4*)(g_h2 + (size_t)s1 * 8 + c * 4);
        acc.x += v0.x * m0 + v1.x * m1;
        acc.y += v0.y * m0 + v1.y * m1;
        acc.z += v0.z * m0 + v1.z * m1;
        acc.w += v0.w * m0 + v1.w * m1;
    }
    if (j < cnt) {
        int s0 = g_esrc[st + j];
        float m0 = g_dinv[s0];
        float4 v0 = *(const float4*)(g_h2 + (size_t)s0 * 8 + c * 4);
        acc.x += v0.x * m0; acc.y += v0.y * m0;
        acc.z += v0.z * m0; acc.w += v0.w * m0;
    }

    float o0 = acc.x * dv + sb2[c * 4 + 0];
    float o1 = acc.y * dv + sb2[c * 4 + 1];
    float o2 = acc.z * dv + sb2[c * 4 + 2];
    float o3 = acc.w * dv + sb2[c * 4 + 3];

    float m = fmaxf(fmaxf(o0, o1), fmaxf(o2, o3));
    m = fmaxf(m, __shfl_xor_sync(0xFFFFFFFFu, m, 1));
    float s = expf(o0 - m) + expf(o1 - m) + expf(o2 - m) + expf(o3 - m);
    s += __shfl_xor_sync(0xFFFFFFFFu, s, 1);
    float l = m + logf(s);

    if (valid) {
        float* op = out + (size_t)node * CD + c * 4;
        op[0] = o0 - l; op[1] = o1 - l; op[2] = o2 - l;
        if (c == 0) op[3] = o3 - l;
    }
}

// ---------------- launch ----------------

extern "C" void kernel_launch(void* const* d_in, const int* in_sizes, int n_in,
                              void* d_out, int out_size) {
    const float* x  = (const float*)d_in[0];
    const int*   ei = (const int*)  d_in[1];
    const float* W1 = (const float*)d_in[2];
    const float* b1 = (const float*)d_in[3];
    const float* W2 = (const float*)d_in[4];
    const float* b2 = (const float*)d_in[5];

    const int n = in_sizes[0] / FIN;
    const int e = in_sizes[1] / 2;
    const int* src = ei;
    const int* dst = ei + e;

    const int NB = (n + 255) / 256;        // gemm node-blocks (391)
    const int GA = NB / 5;                 // gemm part A (overlaps edge count)
    const int GB = NB - GA;                // gemm part B (overlaps CSR fill)
    const int nbScan = (n + 1023) / 1024;  // 98 <= 148 (must stay resident)

    k_zero     <<<(n + 255) / 256, 256>>>(n);
    kA         <<<GA + 768, 256>>>(dst, e, x, W1, n, GA);
    k_scan_all <<<nbScan, 256>>>(n, nbScan);
    kB         <<<GB + 1536, 256>>>(src, dst, e, x, W1, n, GB, GA);
    k_agg1     <<<(n + 63) / 64, 256>>>(b1, W2, n);
    k_agg2     <<<(n + 127) / 128, 256>>>(b2, (float*)d_out, n);
}

// round 6
// speedup vs baseline: 1.1886x; 1.0573x over previous
#include <cuda_runtime.h>
#include <math.h>

#define FIN 512
#define HD  16
#define CD  7
#define NMAX 100000
#define EMAX 3200000

typedef unsigned long long u64;

// ---------------- scratch (static device globals) ----------------
__device__ int   g_cnt [NMAX];        // in-degree (w/o self-loop); re-zeroed by scan
__device__ int   g_rows[NMAX + 1];    // CSR row starts (+ total at [n])
__device__ int   g_cur [NMAX];        // fill cursor
__device__ int   g_bsum[128];         // scan block sums
__device__ float g_dinv[NMAX];
__device__ int   g_esrc[EMAX];        // CSR: source node per edge slot
__device__ float g_h1  [NMAX * HD];
__device__ float g_h2  [NMAX * 8];    // 7 classes padded to 8 (col7 == 0)
__device__ volatile int g_bar;        // spin-barrier arrive counter
__device__ volatile int g_flag;       // spin-barrier release flag
__device__ volatile int g_done;       // exit counter (self-reset)

// ---------------- f32x2 helpers ----------------
__device__ __forceinline__ u64 pk2(float lo, float hi) {
    u64 r; asm("mov.b64 %0, {%1, %2};" : "=l"(r) : "f"(lo), "f"(hi)); return r;
}
__device__ __forceinline__ void upk2(float& lo, float& hi, u64 v) {
    asm("mov.b64 {%0, %1}, %2;" : "=f"(lo), "=f"(hi) : "l"(v));
}
__device__ __forceinline__ void fma2(u64& d, u64 a, u64 b) {
    asm("fma.rn.f32x2 %0, %1, %2, %0;" : "+l"(d) : "l"(a), "l"(b));
}

// ---------------- GEMM1 block: h1[tile] = x[tile] @ W1 ----------------
// 256 threads -> 256 nodes x 16 cols, 16-k subtiles (low register pressure).
// Thread (ng=t>>2, jg=t&3): nodes ng*4..+3 x cols jg*4..+3 as f32x2 node-pairs.
__device__ __forceinline__ void gemm1_block(const float* __restrict__ x,
                                            const float* __restrict__ W1,
                                            int n, int bid) {
    __shared__ float4 sW4[64];           // 16 k x 16 j
    __shared__ float  sXT[16 * 260];     // k-major: [k][node], stride 260

    const int t  = threadIdx.x;
    const int n0 = bid * 256;
    const int ng = t >> 2;
    const int jg = t & 3;

    u64 acc[2][4];
#pragma unroll
    for (int p = 0; p < 2; p++)
#pragma unroll
        for (int c = 0; c < 4; c++) acc[p][c] = 0ull;

    float4 rx[4];
    float4 rw = make_float4(0.f, 0.f, 0.f, 0.f);

    // prologue: stage subtile k0=0  (256 nodes x 16 k = 1024 float4)
    if (t < 64) rw = *(const float4*)(W1 + (size_t)(t >> 2) * HD + (t & 3) * 4);
#pragma unroll
    for (int i = 0; i < 4; i++) {
        int f = t + 256 * i;
        int node = n0 + (f >> 2);
        int kq = f & 3;
        rx[i] = (node < n) ? *(const float4*)(x + (size_t)node * FIN + kq * 4)
                           : make_float4(0.f, 0.f, 0.f, 0.f);
    }

#pragma unroll 1
    for (int k0 = 0; k0 < FIN; k0 += 16) {
        if (t < 64) sW4[t] = rw;
#pragma unroll
        for (int i = 0; i < 4; i++) {
            int f = t + 256 * i;
            int nl = f >> 2;
            int kq = f & 3;
            float* sp = &sXT[(kq * 4) * 260 + nl];
            sp[0]   = rx[i].x;
            sp[260] = rx[i].y;
            sp[520] = rx[i].z;
            sp[780] = rx[i].w;
        }
        __syncthreads();
        bool more = (k0 + 16 < FIN);
        if (more) {   // prefetch next subtile while computing
            if (t < 64)
                rw = *(const float4*)(W1 + (size_t)(k0 + 16 + (t >> 2)) * HD + (t & 3) * 4);
#pragma unroll
            for (int i = 0; i < 4; i++) {
                int f = t + 256 * i;
                int node = n0 + (f >> 2);
                int kq = f & 3;
                rx[i] = (node < n)
                      ? *(const float4*)(x + (size_t)node * FIN + k0 + 16 + kq * 4)
                      : make_float4(0.f, 0.f, 0.f, 0.f);
            }
        }
#pragma unroll
        for (int k = 0; k < 16; k++) {
            const float* xb = &sXT[k * 260 + ng * 4];   // 16B aligned
            u64 x01 = *(const u64*)xb;
            u64 x23 = *(const u64*)(xb + 2);
            float4 wv = sW4[k * 4 + jg];
            u64 w0 = pk2(wv.x, wv.x);
            u64 w1 = pk2(wv.y, wv.y);
            u64 w2 = pk2(wv.z, wv.z);
            u64 w3 = pk2(wv.w, wv.w);
            fma2(acc[0][0], x01, w0); fma2(acc[1][0], x23, w0);
            fma2(acc[0][1], x01, w1); fma2(acc[1][1], x23, w1);
            fma2(acc[0][2], x01, w2); fma2(acc[1][2], x23, w2);
            fma2(acc[0][3], x01, w3); fma2(acc[1][3], x23, w3);
        }
        if (more) __syncthreads();
    }

#pragma unroll
    for (int p = 0; p < 2; p++) {
        float lo[4], hi[4];
#pragma unroll
        for (int c = 0; c < 4; c++) upk2(lo[c], hi[c], acc[p][c]);
        int node0 = n0 + ng * 4 + p * 2;
        if (node0 < n)
            *(float4*)&g_h1[(size_t)node0 * HD + jg * 4] =
                make_float4(lo[0], lo[1], lo[2], lo[3]);
        if (node0 + 1 < n)
            *(float4*)&g_h1[(size_t)(node0 + 1) * HD + jg * 4] =
                make_float4(hi[0], hi[1], hi[2], hi[3]);
    }
}

// ---------------- launch A: degree count overlapped with GEMM part A ----------------

__global__ __launch_bounds__(256, 3) void kA(const int* __restrict__ dst, int e,
                                             const float* __restrict__ x,
                                             const float* __restrict__ W1, int n,
                                             int gemmBlocks) {
    if ((int)blockIdx.x < gemmBlocks) { gemm1_block(x, W1, n, blockIdx.x); return; }
    int nb = gridDim.x - gemmBlocks;
    int b  = blockIdx.x - gemmBlocks;
    for (int i = b * 256 + threadIdx.x; i < e; i += nb * 256)
        atomicAdd(&g_cnt[dst[i]], 1);
}

// ---------------- launch B: CSR fill overlapped with GEMM part B ----------------

__global__ __launch_bounds__(256, 3) void kB(const int* __restrict__ src,
                                             const int* __restrict__ dst, int e,
                                             const float* __restrict__ x,
                                             const float* __restrict__ W1, int n,
                                             int gemmBlocks, int gemmOffset) {
    if ((int)blockIdx.x < gemmBlocks) {
        gemm1_block(x, W1, n, gemmOffset + blockIdx.x);
        return;
    }
    int nb = gridDim.x - gemmBlocks;
    int b  = blockIdx.x - gemmBlocks;
    for (int i = b * 256 + threadIdx.x; i < e; i += nb * 256) {
        int s = src[i], d = dst[i];
        int pos = atomicAdd(&g_cur[d], 1);
        g_esrc[pos] = s;
    }
}

// ---------------- single-kernel scan (+rsqrt, +cnt re-zero, self-reset barrier) ----
// Grid must be <= 148 blocks (all resident). nb = ceil(n/1024) = 98 here.

__global__ __launch_bounds__(256) void k_scan_all(int n, int nb) {
    __shared__ int s[256];
    const int t = threadIdx.x;
    const int b = blockIdx.x;

    int base = b * 1024 + t * 4;
    int v0 = (base + 0 < n) ? g_cnt[base + 0] : 0;
    int v1 = (base + 1 < n) ? g_cnt[base + 1] : 0;
    int v2 = (base + 2 < n) ? g_cnt[base + 2] : 0;
    int v3 = (base + 3 < n) ? g_cnt[base + 3] : 0;
    if (base + 0 < n) g_dinv[base + 0] = rsqrtf((float)(v0 + 1));
    if (base + 1 < n) g_dinv[base + 1] = rsqrtf((float)(v1 + 1));
    if (base + 2 < n) g_dinv[base + 2] = rsqrtf((float)(v2 + 1));
    if (base + 3 < n) g_dinv[base + 3] = rsqrtf((float)(v3 + 1));
    int ts = v0 + v1 + v2 + v3;
    s[t] = ts;
    __syncthreads();
#pragma unroll
    for (int off = 1; off < 256; off <<= 1) {
        int xv = (t >= off) ? s[t - off] : 0;
        __syncthreads();
        s[t] += xv;
        __syncthreads();
    }
    int excl = s[t] - ts;

    if (t == 255) {
        g_bsum[b] = s[255];
        __threadfence();
        atomicAdd((int*)&g_bar, 1);
    }

    if (b == 0) {
        if (t == 0) {
            while (g_bar < nb) { }
            int acc2 = 0;
            for (int i = 0; i < nb; i++) { int v = g_bsum[i]; g_bsum[i] = acc2; acc2 += v; }
            g_rows[n] = acc2;          // total edge count -> rows[n]
            __threadfence();
            g_flag = 1;
        }
        __syncthreads();
    } else {
        if (t == 0) {
            while (g_flag == 0) { }
            __threadfence();
        }
        __syncthreads();
    }

    int off = g_bsum[b];
    int r = excl + off;
    if (base + 0 < n) { g_rows[base + 0] = r; g_cur[base + 0] = r; g_cnt[base + 0] = 0; r += v0; }
    if (base + 1 < n) { g_rows[base + 1] = r; g_cur[base + 1] = r; g_cnt[base + 1] = 0; r += v1; }
    if (base + 2 < n) { g_rows[base + 2] = r; g_cur[base + 2] = r; g_cnt[base + 2] = 0; r += v2; }
    if (base + 3 < n) { g_rows[base + 3] = r; g_cur[base + 3] = r; g_cnt[base + 3] = 0; }

    // self-reset: last block out restores barrier state for the next replay
    __syncthreads();
    if (t == 0) {
        int d = atomicAdd((int*)&g_done, 1);
        if (d == nb - 1) { g_bar = 0; g_flag = 0; g_done = 0; }
    }
}

// ---------------- agg layer 1 + fused layer-2 transform ----------------
// 4 lanes per node; lane c owns feats [4c,4c+4). dinv[s] gathered from L2.

__global__ __launch_bounds__(256) void k_agg1(const float* __restrict__ b1,
                                              const float* __restrict__ W2, int n) {
    __shared__ float sW2[HD * 8];
    __shared__ float sb1[HD];
    int t = threadIdx.x;
    if (t < HD * 8) {
        int j = t >> 3, cc = t & 7;
        sW2[t] = (cc < CD) ? W2[j * CD + cc] : 0.f;
    } else if (t < HD * 8 + HD) {
        sb1[t - HD * 8] = b1[t - HD * 8];
    }
    __syncthreads();

    int node = blockIdx.x * 64 + (t >> 2);
    int c = t & 3;
    bool valid = node < n;
    if (!valid) node = n - 1;

    float dv = g_dinv[node];
    float4 h = *(const float4*)(g_h1 + (size_t)node * HD + c * 4);
    float4 acc = make_float4(h.x * dv, h.y * dv, h.z * dv, h.w * dv);

    int st = g_rows[node];
    int cnt = g_rows[node + 1] - st;
    int j = 0;
    for (; j + 1 < cnt; j += 2) {
        int s0 = g_esrc[st + j], s1 = g_esrc[st + j + 1];
        float m0 = g_dinv[s0],   m1 = g_dinv[s1];
        float4 v0 = *(const float4*)(g_h1 + (size_t)s0 * HD + c * 4);
        float4 v1 = *(const float4*)(g_h1 + (size_t)s1 * HD + c * 4);
        acc.x += v0.x * m0 + v1.x * m1;
        acc.y += v0.y * m0 + v1.y * m1;
        acc.z += v0.z * m0 + v1.z * m1;
        acc.w += v0.w * m0 + v1.w * m1;
    }
    if (j < cnt) {
        int s0 = g_esrc[st + j];
        float m0 = g_dinv[s0];
        float4 v0 = *(const float4*)(g_h1 + (size_t)s0 * HD + c * 4);
        acc.x += v0.x * m0; acc.y += v0.y * m0;
        acc.z += v0.z * m0; acc.w += v0.w * m0;
    }

    float v0 = fmaxf(acc.x * dv + sb1[c * 4 + 0], 0.f);
    float v1 = fmaxf(acc.y * dv + sb1[c * 4 + 1], 0.f);
    float v2 = fmaxf(acc.z * dv + sb1[c * 4 + 2], 0.f);
    float v3 = fmaxf(acc.w * dv + sb1[c * 4 + 3], 0.f);

    float p[8];
#pragma unroll
    for (int cc = 0; cc < 8; cc++) {
        p[cc] = v0 * sW2[(c * 4 + 0) * 8 + cc]
              + v1 * sW2[(c * 4 + 1) * 8 + cc]
              + v2 * sW2[(c * 4 + 2) * 8 + cc]
              + v3 * sW2[(c * 4 + 3) * 8 + cc];
    }
#pragma unroll
    for (int cc = 0; cc < 8; cc++) {
        p[cc] += __shfl_xor_sync(0xFFFFFFFFu, p[cc], 1);
        p[cc] += __shfl_xor_sync(0xFFFFFFFFu, p[cc], 2);
    }
    if (valid) {
        if (c == 0)
            *(float4*)(g_h2 + (size_t)node * 8)     = make_float4(p[0], p[1], p[2], p[3]);
        else if (c == 1)
            *(float4*)(g_h2 + (size_t)node * 8 + 4) = make_float4(p[4], p[5], p[6], 0.f);
    }
}

// ---------------- agg layer 2 + fused bias + log_softmax ----------------

__global__ __launch_bounds__(256) void k_agg2(const float* __restrict__ b2,
                                              float* __restrict__ out, int n) {
    __shared__ float sb2[8];
    int t = threadIdx.x;
    if (t < 8) sb2[t] = (t < CD) ? b2[t] : -1e30f;   // pad lane -> exp()==0
    __syncthreads();

    int node = blockIdx.x * 128 + (t >> 1);
    int c = t & 1;
    bool valid = node < n;
    if (!valid) node = n - 1;

    float dv = g_dinv[node];
    float4 h = *(const float4*)(g_h2 + (size_t)node * 8 + c * 4);
    float4 acc = make_float4(h.x * dv, h.y * dv, h.z * dv, h.w * dv);

    int st = g_rows[node];
    int cnt = g_rows[node + 1] - st;
    int j = 0;
    for (; j + 1 < cnt; j += 2) {
        int s0 = g_esrc[st + j], s1 = g_esrc[st + j + 1];
        float m0 = g_dinv[s0],   m1 = g_dinv[s1];
        float4 v0 = *(const float4*)(g_h2 + (size_t)s0 * 8 + c * 4);
        float4 v1 = *(const float4*)(g_h2 + (size_t)s1 * 8 + c * 4);
        acc.x += v0.x * m0 + v1.x * m1;
        acc.y += v0.y * m0 + v1.y * m1;
        acc.z += v0.z * m0 + v1.z * m1;
        acc.w += v0.w * m0 + v1.w * m1;
    }
    if (j < cnt) {
        int s0 = g_esrc[st + j];
        float m0 = g_dinv[s0];
        float4 v0 = *(const float4*)(g_h2 + (size_t)s0 * 8 + c * 4);
        acc.x += v0.x * m0; acc.y += v0.y * m0;
        acc.z += v0.z * m0; acc.w += v0.w * m0;
    }

    float o0 = acc.x * dv + sb2[c * 4 + 0];
    float o1 = acc.y * dv + sb2[c * 4 + 1];
    float o2 = acc.z * dv + sb2[c * 4 + 2];
    float o3 = acc.w * dv + sb2[c * 4 + 3];

    float m = fmaxf(fmaxf(o0, o1), fmaxf(o2, o3));
    m = fmaxf(m, __shfl_xor_sync(0xFFFFFFFFu, m, 1));
    float s = expf(o0 - m) + expf(o1 - m) + expf(o2 - m) + expf(o3 - m);
    s += __shfl_xor_sync(0xFFFFFFFFu, s, 1);
    float l = m + logf(s);

    if (valid) {
        float* op = out + (size_t)node * CD + c * 4;
        op[0] = o0 - l; op[1] = o1 - l; op[2] = o2 - l;
        if (c == 0) op[3] = o3 - l;
    }
}

// ---------------- launch ----------------

extern "C" void kernel_launch(void* const* d_in, const int* in_sizes, int n_in,
                              void* d_out, int out_size) {
    const float* x  = (const float*)d_in[0];
    const int*   ei = (const int*)  d_in[1];
    const float* W1 = (const float*)d_in[2];
    const float* b1 = (const float*)d_in[3];
    const float* W2 = (const float*)d_in[4];
    const float* b2 = (const float*)d_in[5];

    const int n = in_sizes[0] / FIN;
    const int e = in_sizes[1] / 2;
    const int* src = ei;
    const int* dst = ei + e;

    const int NB = (n + 255) / 256;        // gemm node-blocks (391)
    const int GA = (NB * 2) / 5;           // gemm part A (overlaps degree count)
    const int GB = NB - GA;                // gemm part B (overlaps CSR fill)
    const int nbScan = (n + 1023) / 1024;  // 98 <= 148 (must stay resident)

    kA         <<<GA + 284, 256>>>(dst, e, x, W1, n, GA);
    k_scan_all <<<nbScan, 256>>>(n, nbScan);
    kB         <<<GB + 213, 256>>>(src, dst, e, x, W1, n, GB, GA);
    k_agg1     <<<(n + 63) / 64, 256>>>(b1, W2, n);
    k_agg2     <<<(n + 127) / 128, 256>>>(b2, (float*)d_out, n);
}